// round 4
// baseline (speedup 1.0000x reference)
#include <cuda_runtime.h>

// shuffleAug: per-sample dihedral transform of two (B,64,128,128) fp32 tensors.
//   if f2 (swap):  src_i = flip_{f0^f4}(j), src_j = flip_{f1^f3}(i)
//   else:          src_i = flip_{f0^f3}(i), src_j = flip_{f1^f4}(j)
//
// R4: one plane per block (4 bands of 32 rows), software-pipelined: band n+1's
// loads are issued before band n's stores, keeping ~8 float4 loads in flight
// per thread. Swap path uses double-buffered padded smem tiles (one sync per
// band). Streaming (.cs) hints on all global traffic.

#define HH 128
#define HWSZ (128 * 128)

__device__ __forceinline__ void load_band_ns(float4 (&v)[4], const float* __restrict__ src,
                                             int band, int lr, int lg, int fi, int fj)
{
    const int r  = 32 * band + lr;
    const int sr = fi ? (HH - 1) - r : r;
    const float* srow = src + (size_t)sr * HH;
    if (!fj) {
        #pragma unroll
        for (int k = 0; k < 4; k++)
            v[k] = __ldcs((const float4*)(srow + 32 * k + 4 * lg));
    } else {
        #pragma unroll
        for (int k = 0; k < 4; k++) {
            float4 t = __ldcs((const float4*)(srow + (HH - 4) - 32 * k - 4 * lg));
            v[k] = make_float4(t.w, t.z, t.y, t.x);
        }
    }
}

__device__ __forceinline__ void load_band_sw(float4 (&v)[4], const float* __restrict__ src,
                                             int band, int lr, int lg, int fi, int fj)
{
    const int i0  = 32 * band;
    const int sj0 = fj ? (HH - 32) - i0 : i0;   // source cols cover v = i
    #pragma unroll
    for (int k = 0; k < 4; k++) {
        const int j0  = 32 * k;
        const int si0 = fi ? (HH - 32) - j0 : j0;   // source rows cover u = j
        v[k] = __ldcs((const float4*)(src + (size_t)(si0 + lr) * HH + sj0 + 4 * lg));
    }
}

__global__ void __launch_bounds__(256) shuffleAug_kernel(
    const float* __restrict__ x1,
    const float* __restrict__ x2,
    const int* __restrict__ fb,   // (5, B) int32
    float* __restrict__ out,
    int B)
{
    __shared__ float tile[2][4][32][33];

    const int plane = blockIdx.x;       // b * 128 + c
    const int b = plane >> 7;
    const int c = plane & 127;

    const int f0 = fb[0 * B + b];
    const int f1 = fb[1 * B + b];
    const int sw = fb[2 * B + b];
    const int f3 = fb[3 * B + b];
    const int f4 = fb[4 * B + b];

    const int fi = sw ? (f0 ^ f4) : (f0 ^ f3);
    const int fj = sw ? (f1 ^ f3) : (f1 ^ f4);

    const float* src;
    float* dst;
    if (c < 64) {
        src = x1 + ((size_t)b * 64 + c) * HWSZ;
        dst = out + ((size_t)b * 64 + c) * HWSZ;
    } else {
        src = x2 + ((size_t)b * 64 + (c - 64)) * HWSZ;
        dst = out + (size_t)B * 64 * HWSZ + ((size_t)b * 64 + (c - 64)) * HWSZ;
    }

    const int tid = threadIdx.x;        // 0..255
    const int lr  = tid >> 3;           // 0..31  row within band
    const int lg  = tid & 7;            // 0..7   float4 group within row

    float4 v[2][4];

    if (!sw) {
        // ---- no transpose: pipelined streaming copy over 4 bands ----
        load_band_ns(v[0], src, 0, lr, lg, fi, fj);
        #pragma unroll
        for (int band = 0; band < 4; band++) {
            const int cur = band & 1, nxt = cur ^ 1;
            if (band < 3)
                load_band_ns(v[nxt], src, band + 1, lr, lg, fi, fj);
            float* drow = dst + (size_t)(32 * band + lr) * HH;
            #pragma unroll
            for (int k = 0; k < 4; k++)
                __stcs((float4*)(drow + 32 * k + 4 * lg), v[cur][k]);
        }
    } else {
        // ---- transpose path: double-buffered smem, one sync per band ----
        load_band_sw(v[0], src, 0, lr, lg, fi, fj);

        const int scol = fj ? 31 - lr : lr;
        const int jl0  = 4 * lg;
        const int r0   = fi ? 31 - jl0 : jl0;
        const int st   = fi ? -1 : 1;

        #pragma unroll
        for (int band = 0; band < 4; band++) {
            const int cur = band & 1, nxt = cur ^ 1;
            if (band < 3)
                load_band_sw(v[nxt], src, band + 1, lr, lg, fi, fj);

            // scatter current band into smem buffer `cur`
            #pragma unroll
            for (int k = 0; k < 4; k++) {
                tile[cur][k][lr][4 * lg + 0] = v[cur][k].x;
                tile[cur][k][lr][4 * lg + 1] = v[cur][k].y;
                tile[cur][k][lr][4 * lg + 2] = v[cur][k].z;
                tile[cur][k][lr][4 * lg + 3] = v[cur][k].w;
            }
            __syncthreads();
            // Safe without a second sync: band+2's scatter into buffer `cur`
            // is preceded in every warp by band+1's __syncthreads, which is
            // after this band's gather in program order.

            float* drow = dst + (size_t)(32 * band + lr) * HH;
            #pragma unroll
            for (int k = 0; k < 4; k++) {
                float4 w;
                w.x = tile[cur][k][r0         ][scol];
                w.y = tile[cur][k][r0 + st    ][scol];
                w.z = tile[cur][k][r0 + 2 * st][scol];
                w.w = tile[cur][k][r0 + 3 * st][scol];
                __stcs((float4*)(drow + 32 * k + 4 * lg), w);
            }
        }
    }
}

extern "C" void kernel_launch(void* const* d_in, const int* in_sizes, int n_in,
                              void* d_out, int out_size)
{
    const float* x1 = (const float*)d_in[0];
    const float* x2 = (const float*)d_in[1];
    const int* fb   = (const int*)d_in[2];
    float* out      = (float*)d_out;

    const int B = in_sizes[2] / 5;      // flip_bits is (5, B)

    dim3 block(256, 1, 1);
    dim3 grid(B * 128, 1, 1);           // one plane per block (4096 for B=32)

    shuffleAug_kernel<<<grid, block>>>(x1, x2, fb, out, B);
}

// round 5
// speedup vs baseline: 1.0051x; 1.0051x over previous
#include <cuda_runtime.h>

// shuffleAug: per-sample dihedral transform of two (B,64,128,128) fp32 tensors.
// Composition of the 5 gathers:
//   if f2 (swap):  src_i = flip_{f0^f4}(j), src_j = flip_{f1^f3}(i)
//   else:          src_i = flip_{f0^f3}(i), src_j = flip_{f1^f4}(j)
// out1 = T(x1), out2 = T(x2) independently.
//
// R5 = R3 structure (4 tiles / block = one 32-row band, MLP=4 front-batched,
// occ ~8 CTA/SM) + .cs streaming hints on all global traffic. R3 vs R4
// established that bandwidth is pinned at ~6.34 TB/s (80% DRAM) regardless of
// MLP/occupancy -> HBM mixed-R/W ceiling; this keeps the best-measured shape.

#define HH 128
#define HWSZ (128 * 128)

__global__ void __launch_bounds__(256) shuffleAug_kernel(
    const float* __restrict__ x1,
    const float* __restrict__ x2,
    const int* __restrict__ fb,   // (5, B) int32
    float* __restrict__ out,
    int B)
{
    __shared__ float tile[4][32][33];

    const int plane = blockIdx.y;       // b * 128 + c
    const int b = plane >> 7;
    const int c = plane & 127;

    const int f0 = fb[0 * B + b];
    const int f1 = fb[1 * B + b];
    const int sw = fb[2 * B + b];
    const int f3 = fb[3 * B + b];
    const int f4 = fb[4 * B + b];

    const int fi = sw ? (f0 ^ f4) : (f0 ^ f3);
    const int fj = sw ? (f1 ^ f3) : (f1 ^ f4);

    const float* src;
    float* dst;
    if (c < 64) {
        src = x1 + ((size_t)b * 64 + c) * HWSZ;
        dst = out + ((size_t)b * 64 + c) * HWSZ;
    } else {
        src = x2 + ((size_t)b * 64 + (c - 64)) * HWSZ;
        dst = out + (size_t)B * 64 * HWSZ + ((size_t)b * 64 + (c - 64)) * HWSZ;
    }

    const int tid = threadIdx.x;        // 0..255
    const int lr  = tid >> 3;           // 0..31  row within tile
    const int lg  = tid & 7;            // 0..7   float4 group within row

    const int i0 = blockIdx.x * 32;     // output band: rows i0..i0+31, all cols

    if (!sw) {
        // ---- no transpose: 4 independent float4 copies per thread ----
        const int r  = i0 + lr;
        const int sr = fi ? (HH - 1) - r : r;
        const float* srow = src + (size_t)sr * HH;
        float4 v[4];
        if (!fj) {
            #pragma unroll
            for (int k = 0; k < 4; k++)
                v[k] = __ldcs((const float4*)(srow + 32 * k + 4 * lg));
        } else {
            #pragma unroll
            for (int k = 0; k < 4; k++) {
                float4 t = __ldcs((const float4*)(srow + (HH - 4) - 32 * k - 4 * lg));
                v[k] = make_float4(t.w, t.z, t.y, t.x);
            }
        }
        float* drow = dst + (size_t)r * HH;
        #pragma unroll
        for (int k = 0; k < 4; k++)
            __stcs((float4*)(drow + 32 * k + 4 * lg), v[k]);
    } else {
        // ---- transpose path: 4 smem tiles, loads front-batched ----
        float4 v[4];
        const int sj0 = fj ? (HH - 32) - i0 : i0;       // source cols cover v=i
        #pragma unroll
        for (int k = 0; k < 4; k++) {
            const int j0  = 32 * k;
            const int si0 = fi ? (HH - 32) - j0 : j0;   // source rows cover u=j
            v[k] = __ldcs((const float4*)(src + (size_t)(si0 + lr) * HH + sj0 + 4 * lg));
        }
        #pragma unroll
        for (int k = 0; k < 4; k++) {
            tile[k][lr][4 * lg + 0] = v[k].x;
            tile[k][lr][4 * lg + 1] = v[k].y;
            tile[k][lr][4 * lg + 2] = v[k].z;
            tile[k][lr][4 * lg + 3] = v[k].w;
        }
        __syncthreads();

        // gather: out(i,j) <- tile row fi?31-jl:jl, col fj?31-il:il
        const int scol = fj ? 31 - lr : lr;
        const int jl0  = 4 * lg;
        const int r0   = fi ? 31 - jl0 : jl0;
        const int st   = fi ? -1 : 1;
        float* drow = dst + (size_t)(i0 + lr) * HH;
        #pragma unroll
        for (int k = 0; k < 4; k++) {
            float4 w;
            w.x = tile[k][r0         ][scol];
            w.y = tile[k][r0 + st    ][scol];
            w.z = tile[k][r0 + 2 * st][scol];
            w.w = tile[k][r0 + 3 * st][scol];
            __stcs((float4*)(drow + 32 * k + 4 * lg), w);
        }
    }
}

extern "C" void kernel_launch(void* const* d_in, const int* in_sizes, int n_in,
                              void* d_out, int out_size)
{
    const float* x1 = (const float*)d_in[0];
    const float* x2 = (const float*)d_in[1];
    const int* fb   = (const int*)d_in[2];
    float* out      = (float*)d_out;

    const int B = in_sizes[2] / 5;      // flip_bits is (5, B)

    dim3 block(256, 1, 1);
    dim3 grid(128 / 32, B * 128, 1);    // 4 bands x 4096 planes

    shuffleAug_kernel<<<grid, block>>>(x1, x2, fb, out, B);
}